// round 8
// baseline (speedup 1.0000x reference)
#include <cuda_runtime.h>

#define N_NODES 50000
#define N_EDGES 200000
#define F_IN 100
#define HID 1024

#define NB_FOLD  (F_IN + 1)                        // 101 fold blocks
#define NB_EDGE  ((N_EDGES + 255) / 256)           // 782 blocks, 1 edge/thread
#define NB_NODE  ((N_NODES * 32 + 255) / 256)      // 6250 blocks, warp-per-node
#define NB_E2    ((N_EDGES / 2 + 255) / 256)       // 391 blocks, 2 edges/thread

// Scratch (no device allocation allowed).
// g_degi starts 0 (zero-init) and is reset to 0 by K2 every run -> every
// graph replay sees a clean state. No init pass needed.
__device__ float g_w[F_IN];
__device__ float g_c;
__device__ int   g_degi[N_NODES];
__device__ float g_dinv[N_NODES];
__device__ float g_p[N_NODES];
__device__ int   g_is64;

// Per-block edge-dtype detect: int64-LE values < 50000 have all-zero odd
// 32-bit words; 128 random int32 endpoints all being zero has prob ~ 0.
__device__ __forceinline__ bool detect_is64_inline(const int* __restrict__ ebuf) {
    __shared__ int nz;
    if (threadIdx.x == 0) nz = 0;
    __syncthreads();
    if (threadIdx.x < 128 && ebuf[2 * threadIdx.x + 1] != 0) nz = 1;
    __syncthreads();
    return nz == 0;
}

// ---------------------------------------------------------------------------
// K1: blocks [0,101) fold w = W1 @ W_head (and c = b1·W_head + b_head);
// blocks [101, 101+NB_EDGE) accumulate in-degree via int atomics (buffer
// starts at 0; self-loop +1 applied in K2). Roles are independent.
// Also block 101 publishes g_is64 for K3.
// ---------------------------------------------------------------------------
__global__ void fold_and_deg(const int* __restrict__ ebuf,
                             const float* __restrict__ W1,
                             const float* __restrict__ b1,
                             const float* __restrict__ Wh,
                             const float* __restrict__ bh) {
    int blk = blockIdx.x;
    int t = threadIdx.x;

    if (blk < NB_FOLD) {
        __shared__ float red[256];
        float acc = 0.f;
        if (blk < F_IN) {
            const float* row = W1 + (long long)blk * HID;
            for (int k = t; k < HID; k += 256) acc += row[k] * Wh[k];
        } else {
            for (int k = t; k < HID; k += 256) acc += b1[k] * Wh[k];
        }
        red[t] = acc;
        __syncthreads();
        for (int s = 128; s > 0; s >>= 1) {
            if (t < s) red[t] += red[t + s];
            __syncthreads();
        }
        if (t == 0) {
            if (blk < F_IN) g_w[blk] = red[0];
            else            g_c     = red[0] + bh[0];
        }
        return;
    }

    bool is64 = detect_is64_inline(ebuf);
    if (blk == NB_FOLD && t == 0) g_is64 = is64 ? 1 : 0;  // publish for K3

    int e = (blk - NB_FOLD) * 256 + t;
    if (e < N_EDGES) {
        long long pos = (long long)N_EDGES + e;
        int dst = is64 ? ((const int2*)ebuf)[pos].x : ebuf[pos];
        if ((unsigned)dst < N_NODES)
            atomicAdd(&g_degi[dst], 1);
    }
}

// ---------------------------------------------------------------------------
// K2: warp-per-node: s = x[n]·w, then finalize inline (degrees are final):
// dinv, p, out = c + s*dinv^2. Resets g_degi[n] to 0 for the next replay.
// ---------------------------------------------------------------------------
__global__ void node_kernel(const float* __restrict__ x, float* __restrict__ out) {
    __shared__ float sw[F_IN];
    int t = threadIdx.x;
    for (int i = t; i < F_IN; i += blockDim.x) sw[i] = g_w[i];
    __syncthreads();

    int node = (blockIdx.x * 256 + t) >> 5;
    int lane = t & 31;
    if (node >= N_NODES) return;

    const float* xr = x + (long long)node * F_IN;
    float acc = xr[lane]      * sw[lane]
              + xr[lane + 32] * sw[lane + 32]
              + xr[lane + 64] * sw[lane + 64];
    if (lane < 4) acc += xr[lane + 96] * sw[lane + 96];

    #pragma unroll
    for (int o = 16; o > 0; o >>= 1)
        acc += __shfl_down_sync(0xffffffffu, acc, o);

    if (lane == 0) {
        int   di  = g_degi[node];
        g_degi[node] = 0;                      // restore for next graph replay
        float d = rsqrtf((float)di + 1.0f);    // +1 self loop
        g_dinv[node] = d;
        g_p[node]    = acc * d;
        out[node]    = g_c + acc * d * d;      // self-loop msg + folded bias
    }
}

// ---------------------------------------------------------------------------
// K3: edge scatter, 2 edges/thread: out[dst] += p[src] * dinv[dst].
// Vectorized index loads; all 4 gathers issued before any atomic.
// ---------------------------------------------------------------------------
__global__ void edge_scatter(const int* __restrict__ ebuf,
                             float* __restrict__ out) {
    int e = (blockIdx.x * 256 + threadIdx.x) * 2;
    if (e >= N_EDGES) return;   // N_EDGES even: no partial pairs

    int s0, s1, d0, d1;
    if (g_is64) {
        int4 vs = ((const int4*)ebuf)[e >> 1];
        int4 vd = ((const int4*)ebuf)[((long long)N_EDGES + e) >> 1];
        s0 = vs.x; s1 = vs.z; d0 = vd.x; d1 = vd.z;
    } else {
        int2 vs = ((const int2*)ebuf)[e >> 1];
        int2 vd = ((const int2*)ebuf)[((long long)N_EDGES + e) >> 1];
        s0 = vs.x; s1 = vs.y; d0 = vd.x; d1 = vd.y;
    }

    bool v0 = (unsigned)s0 < N_NODES && (unsigned)d0 < N_NODES;
    bool v1 = (unsigned)s1 < N_NODES && (unsigned)d1 < N_NODES;

    float p0 = v0 ? g_p[s0] : 0.f;
    float p1 = v1 ? g_p[s1] : 0.f;
    float q0 = v0 ? g_dinv[d0] : 0.f;
    float q1 = v1 ? g_dinv[d1] : 0.f;

    if (v0) atomicAdd(&out[d0], p0 * q0);
    if (v1) atomicAdd(&out[d1], p1 * q1);
}

extern "C" void kernel_launch(void* const* d_in, const int* in_sizes, int n_in,
                              void* d_out, int out_size) {
    const float* state = (const float*)d_in[0];  // [N, 100, 1] f32
    const int*   ebuf  = (const int*)  d_in[1];  // [2, 200000] int32/int64 layout
    const float* W1    = (const float*)d_in[2];  // [100, 1024]
    const float* b1    = (const float*)d_in[3];  // [1024]
    const float* Wh    = (const float*)d_in[4];  // [1024, 1]
    const float* bh    = (const float*)d_in[5];  // [1]
    float* out = (float*)d_out;                  // [N, 1]

    fold_and_deg<<<NB_FOLD + NB_EDGE, 256>>>(ebuf, W1, b1, Wh, bh);
    node_kernel <<<NB_NODE, 256>>>(state, out);
    edge_scatter<<<NB_E2, 256>>>(ebuf, out);
}

// round 9
// speedup vs baseline: 2.2883x; 2.2883x over previous
#include <cuda_runtime.h>

#define N_NODES 50000
#define N_EDGES 200000
#define F_IN 100
#define HID 1024

// Kernel A block-role layout (producers get the lowest IDs -> resident first)
#define NBW 101                     // fold blocks: 0..99 rows, 100 = c + is64
#define NBI 196                     // deg-init blocks
#define NBE 782                     // edge degree-atomic blocks
#define NBD 6250                    // dot blocks (warp-per-node)
#define A_EDGE0 (NBW + NBI)         // 297
#define A_DOT0  (A_EDGE0 + NBE)     // 1079
#define A_GRID  (A_DOT0 + NBD)      // 7329

// Kernel B layout
#define NBF 196                     // finalize blocks
#define NBS 391                     // scatter blocks (2 edges/thread)
#define B_GRID (NBF + NBS)

// Scratch (no device allocation allowed)
__device__ float g_w[F_IN];
__device__ float g_c;
__device__ float g_deg[N_NODES];
__device__ float g_dinv[N_NODES];
__device__ float g_s[N_NODES];
__device__ float g_p[N_NODES];
__device__ int   g_is64;

// producer->consumer counters (A resets B's, B resets A's; zero-init works
// for the very first run)
__device__ int cnt_w;   // fold blocks done
__device__ int cnt_d;   // deg-init blocks done
__device__ int cnt_f;   // finalize blocks done

__device__ __forceinline__ void spin_until(volatile int* c, int target) {
    if (threadIdx.x == 0) {
        while (*c < target) { __nanosleep(32); }
        __threadfence();
    }
    __syncthreads();
}

__device__ __forceinline__ void signal(int* c) {
    __syncthreads();
    if (threadIdx.x == 0) {
        __threadfence();
        atomicAdd(c, 1);
    }
}

// Per-block edge-dtype detect: int64-LE values < 50000 have all-zero odd
// 32-bit words; 128 random int32 endpoints all zero has prob ~ 0.
__device__ __forceinline__ bool detect_is64_inline(const int* __restrict__ ebuf,
                                                   int* nzsh) {
    if (threadIdx.x == 0) *nzsh = 0;
    __syncthreads();
    if (threadIdx.x < 128 && ebuf[2 * threadIdx.x + 1] != 0) *nzsh = 1;
    __syncthreads();
    return *nzsh == 0;
}

// ---------------------------------------------------------------------------
// Kernel A: fold || deg-init || deg-atomics(spin init) || dot(spin fold)
// ---------------------------------------------------------------------------
__global__ void __launch_bounds__(256)
kernelA(const float* __restrict__ x,
        const int*   __restrict__ ebuf,
        const float* __restrict__ W1,
        const float* __restrict__ b1,
        const float* __restrict__ Wh,
        const float* __restrict__ bh) {
    const int blk = blockIdx.x;
    const int t   = threadIdx.x;
    __shared__ float sh[256];
    __shared__ int   nzsh;

    if (blk < NBW) {
        // ---- fold producers ----
        if (blk == 0 && t == 0) cnt_f = 0;   // reset kernel B's counter
        float acc = 0.f;
        if (blk < F_IN) {
            const float* row = W1 + (long long)blk * HID;
            for (int k = t; k < HID; k += 256) acc += row[k] * Wh[k];
        } else {
            for (int k = t; k < HID; k += 256) acc += b1[k] * Wh[k];
        }
        sh[t] = acc;
        __syncthreads();
        for (int s = 128; s > 0; s >>= 1) {
            if (t < s) sh[t] += sh[t + s];
            __syncthreads();
        }
        if (t == 0) {
            if (blk < F_IN) g_w[blk] = sh[0];
            else            g_c     = sh[0] + bh[0];
        }
        if (blk == F_IN) {  // block 100 also publishes is64 for kernel B
            bool is64 = detect_is64_inline(ebuf, &nzsh);
            if (t == 0) g_is64 = is64 ? 1 : 0;
        }
        signal(&cnt_w);
        return;
    }

    if (blk < A_EDGE0) {
        // ---- degree init producers ----
        int i = (blk - NBW) * 256 + t;
        if (i < N_NODES) g_deg[i] = 1.0f;    // self loop
        signal(&cnt_d);
        return;
    }

    if (blk < A_DOT0) {
        // ---- edge degree atomics (need deg init) ----
        bool is64 = detect_is64_inline(ebuf, &nzsh);   // no cross-block dep
        spin_until(&cnt_d, NBI);
        int e = (blk - A_EDGE0) * 256 + t;
        if (e < N_EDGES) {
            long long pos = (long long)N_EDGES + e;
            int dst = is64 ? ((const int2*)ebuf)[pos].x : ebuf[pos];
            if ((unsigned)dst < N_NODES)
                atomicAdd(&g_deg[dst], 1.0f);
        }
        return;
    }

    // ---- dot blocks: warp-per-node s[n] = x[n]·w (need w) ----
    spin_until(&cnt_w, NBW);
    for (int i = t; i < F_IN; i += 256) sh[i] = g_w[i];
    __syncthreads();

    int node = ((blk - A_DOT0) * 256 + t) >> 5;
    int lane = t & 31;
    if (node >= N_NODES) return;

    const float* xr = x + (long long)node * F_IN;
    float acc = xr[lane]      * sh[lane]
              + xr[lane + 32] * sh[lane + 32]
              + xr[lane + 64] * sh[lane + 64];
    if (lane < 4) acc += xr[lane + 96] * sh[lane + 96];

    #pragma unroll
    for (int o = 16; o > 0; o >>= 1)
        acc += __shfl_down_sync(0xffffffffu, acc, o);

    if (lane == 0) g_s[node] = acc;
}

// ---------------------------------------------------------------------------
// Kernel B: finalize (coalesced) then scatter (spins on finalize counter)
// ---------------------------------------------------------------------------
__global__ void __launch_bounds__(256)
kernelB(const int* __restrict__ ebuf, float* __restrict__ out) {
    const int blk = blockIdx.x;
    const int t   = threadIdx.x;

    if (blk < NBF) {
        // ---- finalize producers: dinv, p, out-init ----
        int n = blk * 256 + t;
        if (n < N_NODES) {
            float d = rsqrtf(g_deg[n]);       // deg >= 1 (self loop)
            float s = g_s[n];
            g_dinv[n] = d;
            g_p[n]    = s * d;
            out[n]    = g_c + s * d * d;      // self-loop msg + folded bias
        }
        signal(&cnt_f);
        return;
    }

    // ---- scatter consumers ----
    if (blk == NBF && t == 0) { cnt_w = 0; cnt_d = 0; }  // reset for next replay
    spin_until(&cnt_f, NBF);

    int e = ((blk - NBF) * 256 + t) * 2;
    if (e >= N_EDGES) return;   // N_EDGES even: no partial pairs

    int s0, s1, d0, d1;
    if (g_is64) {
        int4 vs = ((const int4*)ebuf)[e >> 1];
        int4 vd = ((const int4*)ebuf)[((long long)N_EDGES + e) >> 1];
        s0 = vs.x; s1 = vs.z; d0 = vd.x; d1 = vd.z;
    } else {
        int2 vs = ((const int2*)ebuf)[e >> 1];
        int2 vd = ((const int2*)ebuf)[((long long)N_EDGES + e) >> 1];
        s0 = vs.x; s1 = vs.y; d0 = vd.x; d1 = vd.y;
    }

    bool v0 = (unsigned)s0 < N_NODES && (unsigned)d0 < N_NODES;
    bool v1 = (unsigned)s1 < N_NODES && (unsigned)d1 < N_NODES;

    float p0 = v0 ? g_p[s0] : 0.f;
    float p1 = v1 ? g_p[s1] : 0.f;
    float q0 = v0 ? g_dinv[d0] : 0.f;
    float q1 = v1 ? g_dinv[d1] : 0.f;

    if (v0) atomicAdd(&out[d0], p0 * q0);
    if (v1) atomicAdd(&out[d1], p1 * q1);
}

extern "C" void kernel_launch(void* const* d_in, const int* in_sizes, int n_in,
                              void* d_out, int out_size) {
    const float* state = (const float*)d_in[0];  // [N, 100, 1] f32
    const int*   ebuf  = (const int*)  d_in[1];  // [2, 200000] int32/int64 layout
    const float* W1    = (const float*)d_in[2];  // [100, 1024]
    const float* b1    = (const float*)d_in[3];  // [1024]
    const float* Wh    = (const float*)d_in[4];  // [1024, 1]
    const float* bh    = (const float*)d_in[5];  // [1]
    float* out = (float*)d_out;                  // [N, 1]

    kernelA<<<A_GRID, 256>>>(state, ebuf, W1, b1, Wh, bh);
    kernelB<<<B_GRID, 256>>>(ebuf, out);
}

// round 10
// speedup vs baseline: 3.4042x; 1.4877x over previous
#include <cuda_runtime.h>

#define N_NODES 50000
#define N_EDGES 200000
#define F_IN 100
#define HID 1024

#define NB_FOLD  (F_IN + 1)                        // 101 fold blocks
#define NB_DEG   ((N_NODES + 255) / 256)           // 196 per-node blocks
#define NB_EDGE  ((N_EDGES + 255) / 256)           // 782 edge blocks (1/thr)
#define NB_NODE  ((N_NODES * 32 + 255) / 256)      // 6250 dot blocks (warp/node)
#define NB_E2    ((N_EDGES / 2 + 255) / 256)       // 391 scatter blocks (2/thr)

// Scratch (no device allocation allowed)
__device__ float g_w[F_IN];
__device__ float g_c;
__device__ float g_deg[N_NODES];
__device__ float g_dinv[N_NODES];
__device__ float g_s[N_NODES];
__device__ float g_p[N_NODES];

// Per-block edge-dtype detect (input-only, no cross-kernel dependency):
// int64-LE values < 50000 have all-zero odd 32-bit words; 128 random int32
// endpoints all being zero has prob ~ 0.
__device__ __forceinline__ bool detect_is64_inline(const int* __restrict__ ebuf) {
    __shared__ int nz;
    if (threadIdx.x == 0) nz = 0;
    __syncthreads();
    if (threadIdx.x < 128 && ebuf[2 * threadIdx.x + 1] != 0) nz = 1;
    __syncthreads();
    return nz == 0;
}

// ---------------------------------------------------------------------------
// K1: fold w = W1 @ W_head (and c) || degree init to 1.0 (self loop)
// ---------------------------------------------------------------------------
__global__ void __launch_bounds__(256)
setup_kernel(const float* __restrict__ W1,
             const float* __restrict__ b1,
             const float* __restrict__ Wh,
             const float* __restrict__ bh) {
    int blk = blockIdx.x;
    int t = threadIdx.x;

    if (blk < NB_FOLD) {
        __shared__ float red[256];
        float acc = 0.f;
        if (blk < F_IN) {
            const float* row = W1 + (long long)blk * HID;
            for (int k = t; k < HID; k += 256) acc += row[k] * Wh[k];
        } else {
            for (int k = t; k < HID; k += 256) acc += b1[k] * Wh[k];
        }
        red[t] = acc;
        __syncthreads();
        for (int s = 128; s > 0; s >>= 1) {
            if (t < s) red[t] += red[t + s];
            __syncthreads();
        }
        if (t == 0) {
            if (blk < F_IN) g_w[blk] = red[0];
            else            g_c     = red[0] + bh[0];
        }
        return;
    }
    int i = (blk - NB_FOLD) * 256 + t;
    if (i < N_NODES) g_deg[i] = 1.0f;
}

// ---------------------------------------------------------------------------
// K2 (PDL): edge blocks first (deg atomics), dot blocks after (s[n]=x[n]·w).
// Input-only prologue runs before cudaGridDependencySynchronize().
// ---------------------------------------------------------------------------
__global__ void __launch_bounds__(256)
dot_and_deg_kernel(const float* __restrict__ x,
                   const int* __restrict__ ebuf) {
    int blk = blockIdx.x;
    int t = threadIdx.x;

    if (blk < NB_EDGE) {
        // prologue: decode dst index (reads only the input edge buffer)
        bool is64 = detect_is64_inline(ebuf);
        int e = blk * 256 + t;
        int dst = -1;
        if (e < N_EDGES) {
            long long pos = (long long)N_EDGES + e;
            dst = is64 ? ((const int2*)ebuf)[pos].x : ebuf[pos];
        }
        cudaGridDependencySynchronize();       // deg init complete
        if ((unsigned)dst < N_NODES)
            atomicAdd(&g_deg[dst], 1.0f);
        return;
    }

    int node = ((blk - NB_EDGE) * 256 + t) >> 5;
    int lane = t & 31;

    // prologue: stream this node's x row (input only)
    float x0 = 0.f, x1 = 0.f, x2 = 0.f, x3 = 0.f;
    if (node < N_NODES) {
        const float* xr = x + (long long)node * F_IN;
        x0 = xr[lane];
        x1 = xr[lane + 32];
        x2 = xr[lane + 64];
        if (lane < 4) x3 = xr[lane + 96];
    }

    cudaGridDependencySynchronize();           // g_w ready

    __shared__ float sw[F_IN];
    for (int i = t; i < F_IN; i += 256) sw[i] = g_w[i];
    __syncthreads();
    if (node >= N_NODES) return;

    float acc = x0 * sw[lane] + x1 * sw[lane + 32] + x2 * sw[lane + 64];
    if (lane < 4) acc += x3 * sw[lane + 96];

    #pragma unroll
    for (int o = 16; o > 0; o >>= 1)
        acc += __shfl_down_sync(0xffffffffu, acc, o);

    if (lane == 0) g_s[node] = acc;
}

// ---------------------------------------------------------------------------
// K3 (PDL): per-node finalize: dinv, p, out = self-loop msg + folded bias
// ---------------------------------------------------------------------------
__global__ void __launch_bounds__(256)
node_finalize(float* __restrict__ out) {
    cudaGridDependencySynchronize();           // deg, s complete
    int n = blockIdx.x * blockDim.x + threadIdx.x;
    if (n < N_NODES) {
        float d = rsqrtf(g_deg[n]);            // deg >= 1 (self loop)
        float s = g_s[n];
        g_dinv[n] = d;
        g_p[n]    = s * d;
        out[n]    = g_c + s * d * d;
    }
}

// ---------------------------------------------------------------------------
// K4 (PDL): edge scatter, 2 edges/thread: out[dst] += p[src] * dinv[dst].
// Edge decode (input only) runs before the dependency sync.
// ---------------------------------------------------------------------------
__global__ void __launch_bounds__(256)
edge_scatter(const int* __restrict__ ebuf,
             float* __restrict__ out) {
    bool is64 = detect_is64_inline(ebuf);
    int e = (blockIdx.x * 256 + threadIdx.x) * 2;

    int s0 = -1, s1 = -1, d0 = -1, d1 = -1;
    if (e < N_EDGES) {   // N_EDGES even: no partial pairs
        if (is64) {
            int4 vs = ((const int4*)ebuf)[e >> 1];
            int4 vd = ((const int4*)ebuf)[((long long)N_EDGES + e) >> 1];
            s0 = vs.x; s1 = vs.z; d0 = vd.x; d1 = vd.z;
        } else {
            int2 vs = ((const int2*)ebuf)[e >> 1];
            int2 vd = ((const int2*)ebuf)[((long long)N_EDGES + e) >> 1];
            s0 = vs.x; s1 = vs.y; d0 = vd.x; d1 = vd.y;
        }
    }
    bool v0 = (unsigned)s0 < N_NODES && (unsigned)d0 < N_NODES;
    bool v1 = (unsigned)s1 < N_NODES && (unsigned)d1 < N_NODES;

    cudaGridDependencySynchronize();           // p, dinv, out-init complete

    float p0 = v0 ? g_p[s0] : 0.f;
    float p1 = v1 ? g_p[s1] : 0.f;
    float q0 = v0 ? g_dinv[d0] : 0.f;
    float q1 = v1 ? g_dinv[d1] : 0.f;

    if (v0) atomicAdd(&out[d0], p0 * q0);
    if (v1) atomicAdd(&out[d1], p1 * q1);
}

// ---------------------------------------------------------------------------
// Host: launch K2..K4 with programmatic stream serialization (PDL)
// ---------------------------------------------------------------------------
template <typename... Args>
static inline void launch_pdl(void (*kern)(Args...), dim3 grid, Args... args) {
    cudaLaunchConfig_t cfg = {};
    cudaLaunchAttribute attr[1];
    attr[0].id = cudaLaunchAttributeProgrammaticStreamSerialization;
    attr[0].val.programmaticStreamSerializationAllowed = 1;
    cfg.gridDim = grid;
    cfg.blockDim = dim3(256, 1, 1);
    cfg.dynamicSmemBytes = 0;
    cfg.stream = 0;
    cfg.attrs = attr;
    cfg.numAttrs = 1;
    cudaLaunchKernelEx(&cfg, kern, args...);
}

extern "C" void kernel_launch(void* const* d_in, const int* in_sizes, int n_in,
                              void* d_out, int out_size) {
    const float* state = (const float*)d_in[0];  // [N, 100, 1] f32
    const int*   ebuf  = (const int*)  d_in[1];  // [2, 200000] int32/int64 layout
    const float* W1    = (const float*)d_in[2];  // [100, 1024]
    const float* b1    = (const float*)d_in[3];  // [1024]
    const float* Wh    = (const float*)d_in[4];  // [1024, 1]
    const float* bh    = (const float*)d_in[5];  // [1]
    float* out = (float*)d_out;                  // [N, 1]

    setup_kernel<<<NB_FOLD + NB_DEG, 256>>>(W1, b1, Wh, bh);
    launch_pdl(dot_and_deg_kernel, dim3(NB_EDGE + NB_NODE, 1, 1), state, ebuf);
    launch_pdl(node_finalize, dim3(NB_DEG, 1, 1), out);
    launch_pdl(edge_scatter, dim3(NB_E2, 1, 1), (const int*)ebuf, (float*)out);
}